// round 2
// baseline (speedup 1.0000x reference)
#include <cuda_runtime.h>
#include <cuda_bf16.h>
#include <math.h>

#define DM 1024

__device__ float g_q[4096 * 1024];
__device__ float g_k[4096 * 1024];
__device__ float g_v[4096 * 1024];
__device__ float g_ctx[4096 * 1024];

__device__ __forceinline__ unsigned pk(__nv_bfloat16 a, __nv_bfloat16 b) {
    __nv_bfloat162 t; t.x = a; t.y = b;
    return *reinterpret_cast<unsigned*>(&t);
}
// split pair (x,y) into hi bf16x2 word and lo bf16x2 word
__device__ __forceinline__ void split2(float x, float y, unsigned& h, unsigned& l) {
    __nv_bfloat16 xh = __float2bfloat16(x), yh = __float2bfloat16(y);
    h = pk(xh, yh);
    l = pk(__float2bfloat16(x - __bfloat162float(xh)),
           __float2bfloat16(y - __bfloat162float(yh)));
}

__device__ __forceinline__ void mma16(float c[4], const unsigned a[4], const unsigned b[2]) {
    asm volatile(
        "mma.sync.aligned.m16n8k16.row.col.f32.bf16.bf16.f32 "
        "{%0,%1,%2,%3},{%4,%5,%6,%7},{%8,%9},{%0,%1,%2,%3};\n"
        : "+f"(c[0]), "+f"(c[1]), "+f"(c[2]), "+f"(c[3])
        : "r"(a[0]), "r"(a[1]), "r"(a[2]), "r"(a[3]), "r"(b[0]), "r"(b[1]));
}

// ============================================================================
// GEMM: C[4096,1024] = alpha * (A[4096,1024] @ B'[1024,1024] + bias)
// BMODE 1: B'[d][h*64+e] = W[h][d][e]   (projection weights [H,1024,64])
// BMODE 2: B'[h*64+e][n] = Wo[e*16+h][n] (output weight row permute)
// DST: 0->g_q 1->g_k 2->g_v else Cout ; ASRC 1 -> A = g_ctx
// ============================================================================
#define AST 9  // words (bf16x2) per row: 8 + 1 pad

template <int BMODE, int DST, int ASRC>
__global__ void __launch_bounds__(256)
gemm128(const float* __restrict__ Ain, const float* __restrict__ Bw,
        const float* __restrict__ bias, float* __restrict__ Cout, float alpha) {
    __shared__ unsigned sAh[128 * AST], sAl[128 * AST];
    __shared__ unsigned sBh[128 * AST], sBl[128 * AST];

    const float* A = (ASRC == 1) ? (const float*)g_ctx : Ain;
    float* C = (DST == 0) ? g_q : (DST == 1) ? g_k : (DST == 2) ? g_v : Cout;

    const int tid = threadIdx.x, lane = tid & 31, warp = tid >> 5;
    const int wm = warp & 3, wn = warp >> 2, g = lane >> 2, tg = lane & 3;
    const int row0 = blockIdx.y * 128, col0 = blockIdx.x * 128;

    float acc[2][8][4] = {};
    float4 pa[2];
    float2 pb0[2], pb1[2];

    auto ldB = [&](int k, int n) -> float2 {
        const float* p;
        if (BMODE == 1) p = Bw + ((n >> 6) * DM + k) * 64 + (n & 63);
        else            p = Bw + ((k & 63) * 16 + (k >> 6)) * DM + n;
        return *(const float2*)p;
    };
    auto gload = [&](int kt) {
#pragma unroll
        for (int i = 0; i < 2; i++) {
            int s = tid + i * 256;
            pa[i] = *(const float4*)(A + (row0 + (s >> 2)) * DM + kt * 16 + (s & 3) * 4);
            int n = col0 + (s & 63) * 2;
            int k = kt * 16 + (s >> 6) * 2;
            pb0[i] = ldB(k, n);
            pb1[i] = ldB(k + 1, n);
        }
    };
    auto sstore = [&]() {
#pragma unroll
        for (int i = 0; i < 2; i++) {
            int s = tid + i * 256;
            int ar = s >> 2, aw = (s & 3) * 2;
            unsigned h0, l0, h1, l1;
            split2(pa[i].x, pa[i].y, h0, l0);
            split2(pa[i].z, pa[i].w, h1, l1);
            sAh[ar * AST + aw] = h0; sAh[ar * AST + aw + 1] = h1;
            sAl[ar * AST + aw] = l0; sAl[ar * AST + aw + 1] = l1;
            int n = (s & 63) * 2, kw = s >> 6;
            split2(pb0[i].x, pb1[i].x, h0, l0);  // col n, k-pair
            split2(pb0[i].y, pb1[i].y, h1, l1);  // col n+1
            sBh[n * AST + kw] = h0;       sBl[n * AST + kw] = l0;
            sBh[(n + 1) * AST + kw] = h1; sBl[(n + 1) * AST + kw] = l1;
        }
    };

    gload(0); sstore(); __syncthreads();

    for (int kt = 0; kt < 64; kt++) {
        if (kt + 1 < 64) gload(kt + 1);
        unsigned ah[2][4], al[2][4], bh[8][2], bl[8][2];
#pragma unroll
        for (int mi = 0; mi < 2; mi++) {
            int rb = (wm * 32 + mi * 16 + g) * AST + tg;
            ah[mi][0] = sAh[rb];           ah[mi][1] = sAh[rb + 8 * AST];
            ah[mi][2] = sAh[rb + 4];       ah[mi][3] = sAh[rb + 8 * AST + 4];
            al[mi][0] = sAl[rb];           al[mi][1] = sAl[rb + 8 * AST];
            al[mi][2] = sAl[rb + 4];       al[mi][3] = sAl[rb + 8 * AST + 4];
        }
#pragma unroll
        for (int ni = 0; ni < 8; ni++) {
            int cb = (wn * 64 + ni * 8 + g) * AST + tg;
            bh[ni][0] = sBh[cb]; bh[ni][1] = sBh[cb + 4];
            bl[ni][0] = sBl[cb]; bl[ni][1] = sBl[cb + 4];
        }
#pragma unroll
        for (int mi = 0; mi < 2; mi++)
#pragma unroll
            for (int ni = 0; ni < 8; ni++) {
                mma16(acc[mi][ni], ah[mi], bh[ni]);
                mma16(acc[mi][ni], al[mi], bh[ni]);
                mma16(acc[mi][ni], ah[mi], bl[ni]);
            }
        __syncthreads();
        if (kt + 1 < 64) { sstore(); }
        __syncthreads();
    }

#pragma unroll
    for (int mi = 0; mi < 2; mi++) {
        int r = row0 + wm * 32 + mi * 16 + g;
#pragma unroll
        for (int ni = 0; ni < 8; ni++) {
            int c = col0 + wn * 64 + ni * 8 + tg * 2;
            float2 bv = *(const float2*)(bias + c);
            *(float2*)(C + r * DM + c) =
                make_float2(alpha * (acc[mi][ni][0] + bv.x), alpha * (acc[mi][ni][1] + bv.y));
            *(float2*)(C + (r + 8) * DM + c) =
                make_float2(alpha * (acc[mi][ni][2] + bv.x), alpha * (acc[mi][ni][3] + bv.y));
        }
    }
}

// ============================================================================
// Flash attention per (b,h): O = softmax(q k^T + maskbias) v  -> g_ctx
// grid (32, 32) = (N/64, B*H), 128 threads. q pre-scaled by 1/8.
// ============================================================================
#define FST 36  // words per row: 32 + 4 pad

__global__ void __launch_bounds__(128) flash_attn(const float* __restrict__ mask) {
    extern __shared__ unsigned sm[];
    unsigned* sQh = sm;              unsigned* sQl = sQh + 64 * FST;
    unsigned* sKh = sQl + 64 * FST;  unsigned* sKl = sKh + 64 * FST;  // reused for P
    unsigned* sVh = sKl + 64 * FST;  unsigned* sVl = sVh + 64 * FST;  // V transposed [e][m/2]

    const int tid = threadIdx.x, lane = tid & 31, warp = tid >> 5;
    const int g = lane >> 2, tg = lane & 3;
    const int bh = blockIdx.y, b = bh >> 4, h = bh & 15;
    const int n0 = blockIdx.x * 64, wrow = warp * 16;

    {   // load Q tile 64x64 (hi/lo words)
        int r = tid >> 1, e0 = (tid & 1) * 32;
        const float* src = g_q + (b * 2048 + n0 + r) * DM + h * 64 + e0;
#pragma unroll
        for (int i = 0; i < 8; i++) {
            float4 v = *(const float4*)(src + i * 4);
            unsigned h0, l0, h1, l1;
            split2(v.x, v.y, h0, l0); split2(v.z, v.w, h1, l1);
            int w = r * FST + (e0 + i * 4) / 2;
            sQh[w] = h0; sQh[w + 1] = h1; sQl[w] = l0; sQl[w + 1] = l1;
        }
    }

    float o[8][4] = {};
    float mr0 = -INFINITY, mr1 = -INFINITY, lr0 = 0.f, lr1 = 0.f;

    for (int mt = 0; mt < 32; mt++) {
        const int m0 = mt * 64;
        __syncthreads();  // prev tile PV done (also publishes sQ on iter 0 path below)
        {   // K tile [m][e/2]
            int r = tid >> 1, e0 = (tid & 1) * 32;
            const float* ks = g_k + (b * 2048 + m0 + r) * DM + h * 64 + e0;
#pragma unroll
            for (int i = 0; i < 8; i++) {
                float4 v = *(const float4*)(ks + i * 4);
                unsigned h0, l0, h1, l1;
                split2(v.x, v.y, h0, l0); split2(v.z, v.w, h1, l1);
                int w = r * FST + (e0 + i * 4) / 2;
                sKh[w] = h0; sKh[w + 1] = h1; sKl[w] = l0; sKl[w + 1] = l1;
            }
            // V transposed: sVt[e][m] as bf16 halfword stores
            int m = tid & 63, eh = (tid >> 6) * 32;
            const float* vs = g_v + (b * 2048 + m0 + m) * DM + h * 64 + eh;
            __nv_bfloat16* vh16 = (__nv_bfloat16*)sVh;
            __nv_bfloat16* vl16 = (__nv_bfloat16*)sVl;
#pragma unroll
            for (int i = 0; i < 8; i++) {
                float4 v = *(const float4*)(vs + i * 4);
                float xs[4] = {v.x, v.y, v.z, v.w};
#pragma unroll
                for (int j = 0; j < 4; j++) {
                    int e = eh + i * 4 + j;
                    __nv_bfloat16 hi = __float2bfloat16(xs[j]);
                    vh16[e * (2 * FST) + m] = hi;
                    vl16[e * (2 * FST) + m] = __float2bfloat16(xs[j] - __bfloat162float(hi));
                }
            }
        }
        __syncthreads();  // tiles ready

        // S = Q K^T
        float s[8][4] = {};
#pragma unroll
        for (int kk = 0; kk < 4; kk++) {
            unsigned ah[4], al[4];
            int rb = (wrow + g) * FST + kk * 8 + tg;
            ah[0] = sQh[rb]; ah[1] = sQh[rb + 8 * FST];
            ah[2] = sQh[rb + 4]; ah[3] = sQh[rb + 8 * FST + 4];
            al[0] = sQl[rb]; al[1] = sQl[rb + 8 * FST];
            al[2] = sQl[rb + 4]; al[3] = sQl[rb + 8 * FST + 4];
#pragma unroll
            for (int ni = 0; ni < 8; ni++) {
                int cb = (ni * 8 + g) * FST + kk * 8 + tg;
                unsigned bb[2] = {sKh[cb], sKh[cb + 4]};
                unsigned cc[2] = {sKl[cb], sKl[cb + 4]};
                mma16(s[ni], ah, bb);
                mma16(s[ni], al, bb);
                mma16(s[ni], ah, cc);
            }
        }

        // mask bias + online softmax
        const float* mrow = mask + (n0 + wrow + g) * 2048 + m0;
        float nm0 = -INFINITY, nm1 = -INFINITY;
#pragma unroll
        for (int ni = 0; ni < 8; ni++) {
            float2 mk0 = *(const float2*)(mrow + ni * 8 + tg * 2);
            float2 mk1 = *(const float2*)(mrow + 8 * 2048 + ni * 8 + tg * 2);
            s[ni][0] += -1e10f * (1.f - mk0.x); s[ni][1] += -1e10f * (1.f - mk0.y);
            s[ni][2] += -1e10f * (1.f - mk1.x); s[ni][3] += -1e10f * (1.f - mk1.y);
            nm0 = fmaxf(nm0, fmaxf(s[ni][0], s[ni][1]));
            nm1 = fmaxf(nm1, fmaxf(s[ni][2], s[ni][3]));
        }
        nm0 = fmaxf(nm0, __shfl_xor_sync(0xffffffffu, nm0, 1));
        nm0 = fmaxf(nm0, __shfl_xor_sync(0xffffffffu, nm0, 2));
        nm1 = fmaxf(nm1, __shfl_xor_sync(0xffffffffu, nm1, 1));
        nm1 = fmaxf(nm1, __shfl_xor_sync(0xffffffffu, nm1, 2));
        float mn0 = fmaxf(mr0, nm0), mn1 = fmaxf(mr1, nm1);
        float sc0 = __expf(mr0 - mn0), sc1 = __expf(mr1 - mn1);
        float rs0 = 0.f, rs1 = 0.f;
#pragma unroll
        for (int ni = 0; ni < 8; ni++) {
            s[ni][0] = __expf(s[ni][0] - mn0); s[ni][1] = __expf(s[ni][1] - mn0);
            s[ni][2] = __expf(s[ni][2] - mn1); s[ni][3] = __expf(s[ni][3] - mn1);
            rs0 += s[ni][0] + s[ni][1];
            rs1 += s[ni][2] + s[ni][3];
        }
        rs0 += __shfl_xor_sync(0xffffffffu, rs0, 1); rs0 += __shfl_xor_sync(0xffffffffu, rs0, 2);
        rs1 += __shfl_xor_sync(0xffffffffu, rs1, 1); rs1 += __shfl_xor_sync(0xffffffffu, rs1, 2);
        lr0 = lr0 * sc0 + rs0; lr1 = lr1 * sc1 + rs1;
        mr0 = mn0; mr1 = mn1;
#pragma unroll
        for (int eb = 0; eb < 8; eb++) {
            o[eb][0] *= sc0; o[eb][1] *= sc0;
            o[eb][2] *= sc1; o[eb][3] *= sc1;
        }

        __syncthreads();  // all warps done reading sK before P overwrite
#pragma unroll
        for (int ni = 0; ni < 8; ni++) {
            unsigned h0, l0;
            split2(s[ni][0], s[ni][1], h0, l0);
            sKh[(wrow + g) * FST + ni * 4 + tg] = h0;
            sKl[(wrow + g) * FST + ni * 4 + tg] = l0;
            split2(s[ni][2], s[ni][3], h0, l0);
            sKh[(wrow + g + 8) * FST + ni * 4 + tg] = h0;
            sKl[(wrow + g + 8) * FST + ni * 4 + tg] = l0;
        }
        __syncwarp();  // P region is warp-private

        // O += P V
#pragma unroll
        for (int kk = 0; kk < 4; kk++) {
            unsigned ah[4], al[4];
            int rb = (wrow + g) * FST + kk * 8 + tg;
            ah[0] = sKh[rb]; ah[1] = sKh[rb + 8 * FST];
            ah[2] = sKh[rb + 4]; ah[3] = sKh[rb + 8 * FST + 4];
            al[0] = sKl[rb]; al[1] = sKl[rb + 8 * FST];
            al[2] = sKl[rb + 4]; al[3] = sKl[rb + 8 * FST + 4];
#pragma unroll
            for (int eb = 0; eb < 8; eb++) {
                int cb = (eb * 8 + g) * FST + kk * 8 + tg;
                unsigned bb[2] = {sVh[cb], sVh[cb + 4]};
                unsigned cc[2] = {sVl[cb], sVl[cb + 4]};
                mma16(o[eb], ah, bb);
                mma16(o[eb], al, bb);
                mma16(o[eb], ah, cc);
            }
        }
    }

    float i0 = 1.f / lr0, i1 = 1.f / lr1;
    float* dst = g_ctx + (b * 2048 + n0 + wrow + g) * DM + h * 64;
#pragma unroll
    for (int eb = 0; eb < 8; eb++) {
        int c = eb * 8 + tg * 2;
        *(float2*)(dst + c) = make_float2(o[eb][0] * i0, o[eb][1] * i0);
        *(float2*)(dst + 8 * DM + c) = make_float2(o[eb][2] * i1, o[eb][3] * i1);
    }
}

extern "C" void kernel_launch(void* const* d_in, const int* in_sizes, int n_in,
                              void* d_out, int out_size) {
    const float* query = (const float*)d_in[0];
    const float* key   = (const float*)d_in[1];
    const float* value = (const float*)d_in[2];
    const float* mask  = (const float*)d_in[3];
    const float* Wq = (const float*)d_in[4];
    const float* bq = (const float*)d_in[5];
    const float* Wk = (const float*)d_in[6];
    const float* bk = (const float*)d_in[7];
    const float* Wv = (const float*)d_in[8];
    const float* bv = (const float*)d_in[9];
    const float* Wo = (const float*)d_in[10];
    const float* bo = (const float*)d_in[11];
    float* out = (float*)d_out;

    cudaFuncSetAttribute(flash_attn, cudaFuncAttributeMaxDynamicSharedMemorySize,
                         6 * 64 * FST * 4);

    dim3 gg(8, 32);
    gemm128<1, 0, 0><<<gg, 256>>>(query, Wq, bq, nullptr, 0.125f);
    gemm128<1, 1, 0><<<gg, 256>>>(key,   Wk, bk, nullptr, 1.f);
    gemm128<1, 2, 0><<<gg, 256>>>(value, Wv, bv, nullptr, 1.f);
    flash_attn<<<dim3(32, 32), 128, 6 * 64 * FST * 4>>>(mask);
    gemm128<2, 3, 1><<<gg, 256>>>(nullptr, Wo, bo, out, 1.f);
}

// round 3
// speedup vs baseline: 1.1747x; 1.1747x over previous
#include <cuda_runtime.h>
#include <cuda_bf16.h>
#include <math.h>

#define DM 1024

__device__ float g_q[4096 * 1024];
__device__ float g_k[4096 * 1024];
__device__ float g_v[4096 * 1024];
__device__ float g_ctx[4096 * 1024];

__device__ __forceinline__ unsigned pk(__nv_bfloat16 a, __nv_bfloat16 b) {
    __nv_bfloat162 t; t.x = a; t.y = b;
    return *reinterpret_cast<unsigned*>(&t);
}
__device__ __forceinline__ void split2(float x, float y, unsigned& h, unsigned& l) {
    __nv_bfloat16 xh = __float2bfloat16(x), yh = __float2bfloat16(y);
    h = pk(xh, yh);
    l = pk(__float2bfloat16(x - __bfloat162float(xh)),
           __float2bfloat16(y - __bfloat162float(yh)));
}
__device__ __forceinline__ void mma16(float c[4], const unsigned a[4], const unsigned b[2]) {
    asm volatile(
        "mma.sync.aligned.m16n8k16.row.col.f32.bf16.bf16.f32 "
        "{%0,%1,%2,%3},{%4,%5,%6,%7},{%8,%9},{%0,%1,%2,%3};\n"
        : "+f"(c[0]), "+f"(c[1]), "+f"(c[2]), "+f"(c[3])
        : "r"(a[0]), "r"(a[1]), "r"(a[2]), "r"(a[3]), "r"(b[0]), "r"(b[1]));
}

// ============================================================================
// GEMM: C[4096,1024] = alpha * (A @ B' + bias), double-buffered smem.
// BMODE 1: B'[d][h*64+e] = W[h][d][e] ; BMODE 2: B'[h*64+e][n] = Wo[e*16+h][n]
// ============================================================================
#define AST 9

template <int BMODE, int DST, int ASRC>
__global__ void __launch_bounds__(256)
gemm128(const float* __restrict__ Ain, const float* __restrict__ Bw,
        const float* __restrict__ bias, float* __restrict__ Cout, float alpha) {
    __shared__ unsigned sAh[2][128 * AST], sAl[2][128 * AST];
    __shared__ unsigned sBh[2][128 * AST], sBl[2][128 * AST];

    const float* A = (ASRC == 1) ? (const float*)g_ctx : Ain;
    float* C = (DST == 0) ? g_q : (DST == 1) ? g_k : (DST == 2) ? g_v : Cout;

    const int tid = threadIdx.x, lane = tid & 31, warp = tid >> 5;
    const int wm = warp & 3, wn = warp >> 2, g = lane >> 2, tg = lane & 3;
    const int row0 = blockIdx.y * 128, col0 = blockIdx.x * 128;

    float acc[2][8][4] = {};
    float4 pa[2];
    float2 pb0[2], pb1[2];

    auto ldB = [&](int k, int n) -> float2 {
        const float* p;
        if (BMODE == 1) p = Bw + ((n >> 6) * DM + k) * 64 + (n & 63);
        else            p = Bw + ((k & 63) * 16 + (k >> 6)) * DM + n;
        return *(const float2*)p;
    };
    auto gload = [&](int kt) {
#pragma unroll
        for (int i = 0; i < 2; i++) {
            int s = tid + i * 256;
            pa[i] = *(const float4*)(A + (row0 + (s >> 2)) * DM + kt * 16 + (s & 3) * 4);
            int n = col0 + (s & 63) * 2;
            int k = kt * 16 + (s >> 6) * 2;
            pb0[i] = ldB(k, n);
            pb1[i] = ldB(k + 1, n);
        }
    };
    auto sstore = [&](int p) {
#pragma unroll
        for (int i = 0; i < 2; i++) {
            int s = tid + i * 256;
            int ar = s >> 2, aw = (s & 3) * 2;
            unsigned h0, l0, h1, l1;
            split2(pa[i].x, pa[i].y, h0, l0);
            split2(pa[i].z, pa[i].w, h1, l1);
            sAh[p][ar * AST + aw] = h0; sAh[p][ar * AST + aw + 1] = h1;
            sAl[p][ar * AST + aw] = l0; sAl[p][ar * AST + aw + 1] = l1;
            int n = (s & 63) * 2, kw = s >> 6;
            split2(pb0[i].x, pb1[i].x, h0, l0);
            split2(pb0[i].y, pb1[i].y, h1, l1);
            sBh[p][n * AST + kw] = h0;       sBl[p][n * AST + kw] = l0;
            sBh[p][(n + 1) * AST + kw] = h1; sBl[p][(n + 1) * AST + kw] = l1;
        }
    };

    gload(0); sstore(0); __syncthreads();

    for (int kt = 0; kt < 64; kt++) {
        const int p = kt & 1;
        if (kt < 63) gload(kt + 1);
        unsigned ah[2][4], al[2][4], bh[8][2], bl[8][2];
#pragma unroll
        for (int mi = 0; mi < 2; mi++) {
            int rb = (wm * 32 + mi * 16 + g) * AST + tg;
            ah[mi][0] = sAh[p][rb];     ah[mi][1] = sAh[p][rb + 8 * AST];
            ah[mi][2] = sAh[p][rb + 4]; ah[mi][3] = sAh[p][rb + 8 * AST + 4];
            al[mi][0] = sAl[p][rb];     al[mi][1] = sAl[p][rb + 8 * AST];
            al[mi][2] = sAl[p][rb + 4]; al[mi][3] = sAl[p][rb + 8 * AST + 4];
        }
#pragma unroll
        for (int ni = 0; ni < 8; ni++) {
            int cb = (wn * 64 + ni * 8 + g) * AST + tg;
            bh[ni][0] = sBh[p][cb]; bh[ni][1] = sBh[p][cb + 4];
            bl[ni][0] = sBl[p][cb]; bl[ni][1] = sBl[p][cb + 4];
        }
#pragma unroll
        for (int mi = 0; mi < 2; mi++)
#pragma unroll
            for (int ni = 0; ni < 8; ni++) mma16(acc[mi][ni], ah[mi], bh[ni]);
#pragma unroll
        for (int mi = 0; mi < 2; mi++)
#pragma unroll
            for (int ni = 0; ni < 8; ni++) mma16(acc[mi][ni], al[mi], bh[ni]);
#pragma unroll
        for (int mi = 0; mi < 2; mi++)
#pragma unroll
            for (int ni = 0; ni < 8; ni++) mma16(acc[mi][ni], ah[mi], bl[ni]);
        if (kt < 63) sstore(p ^ 1);
        __syncthreads();
    }

#pragma unroll
    for (int mi = 0; mi < 2; mi++) {
        int r = row0 + wm * 32 + mi * 16 + g;
#pragma unroll
        for (int ni = 0; ni < 8; ni++) {
            int c = col0 + wn * 64 + ni * 8 + tg * 2;
            float2 bv = *(const float2*)(bias + c);
            *(float2*)(C + r * DM + c) =
                make_float2(alpha * (acc[mi][ni][0] + bv.x), alpha * (acc[mi][ni][1] + bv.y));
            *(float2*)(C + (r + 8) * DM + c) =
                make_float2(alpha * (acc[mi][ni][2] + bv.x), alpha * (acc[mi][ni][3] + bv.y));
        }
    }
}

// ============================================================================
// Flash attention v2: CTA = 128 Q rows, 4 warps x 32 rows. Q frags persistent
// in registers; P kept in registers (acc layout == A-frag layout). K/V in smem.
// grid (16, 32) = (N/128, B*H), 128 threads.
// ============================================================================
#define FST 36

__global__ void __launch_bounds__(128) flash_attn(const float* __restrict__ mask) {
    __shared__ unsigned sKh[64 * FST], sKl[64 * FST];
    __shared__ unsigned sVh[64 * FST], sVl[64 * FST];   // V transposed [e][m]

    const int tid = threadIdx.x, lane = tid & 31, warp = tid >> 5;
    const int g = lane >> 2, tg = lane & 3;
    const int bh = blockIdx.y, b = bh >> 4, h = bh & 15;
    const int n0 = blockIdx.x * 128, wrow = warp * 32;

    // Q fragments in registers (persistent): rows wrow + mi*16 + {g, g+8}
    unsigned qh[2][4][4], ql[2][4][4];
    {
        const float* qb = g_q + (b * 2048 + n0 + wrow) * DM + h * 64;
#pragma unroll
        for (int mi = 0; mi < 2; mi++)
#pragma unroll
            for (int kk = 0; kk < 4; kk++) {
                int r0 = mi * 16 + g, r1 = r0 + 8, e = kk * 16 + 2 * tg;
                float2 x0 = *(const float2*)(qb + r0 * DM + e);
                float2 x1 = *(const float2*)(qb + r1 * DM + e);
                float2 x2 = *(const float2*)(qb + r0 * DM + e + 8);
                float2 x3 = *(const float2*)(qb + r1 * DM + e + 8);
                split2(x0.x, x0.y, qh[mi][kk][0], ql[mi][kk][0]);
                split2(x1.x, x1.y, qh[mi][kk][1], ql[mi][kk][1]);
                split2(x2.x, x2.y, qh[mi][kk][2], ql[mi][kk][2]);
                split2(x3.x, x3.y, qh[mi][kk][3], ql[mi][kk][3]);
            }
    }

    float o[2][8][4] = {};
    float mr[2][2] = {{-INFINITY, -INFINITY}, {-INFINITY, -INFINITY}};
    float lr[2][2] = {{0.f, 0.f}, {0.f, 0.f}};

    for (int mt = 0; mt < 32; mt++) {
        const int m0 = mt * 64;
        __syncthreads();  // previous PV done before K/V overwrite
        {   // K tile [m][e]: hi/lo bf16x2 words
            int r = tid >> 1, e0 = (tid & 1) * 32;
            const float* ks = g_k + (b * 2048 + m0 + r) * DM + h * 64 + e0;
#pragma unroll
            for (int i = 0; i < 8; i++) {
                float4 v = *(const float4*)(ks + i * 4);
                unsigned h0, l0, h1, l1;
                split2(v.x, v.y, h0, l0); split2(v.z, v.w, h1, l1);
                int w = r * FST + (e0 + i * 4) / 2;
                sKh[w] = h0; sKh[w + 1] = h1; sKl[w] = l0; sKl[w + 1] = l1;
            }
            // V transposed: bf16 halfword stores
            int m = tid & 63, eh = (tid >> 6) * 32;
            const float* vs = g_v + (b * 2048 + m0 + m) * DM + h * 64 + eh;
            __nv_bfloat16* vh16 = (__nv_bfloat16*)sVh;
            __nv_bfloat16* vl16 = (__nv_bfloat16*)sVl;
#pragma unroll
            for (int i = 0; i < 8; i++) {
                float4 v = *(const float4*)(vs + i * 4);
                float xs[4] = {v.x, v.y, v.z, v.w};
#pragma unroll
                for (int j = 0; j < 4; j++) {
                    int e = eh + i * 4 + j;
                    __nv_bfloat16 hi = __float2bfloat16(xs[j]);
                    vh16[e * (2 * FST) + m] = hi;
                    vl16[e * (2 * FST) + m] = __float2bfloat16(xs[j] - __bfloat162float(hi));
                }
            }
        }
        __syncthreads();

        // S = Q K^T
        float s[2][8][4] = {};
#pragma unroll
        for (int kk = 0; kk < 4; kk++)
#pragma unroll
            for (int ni = 0; ni < 8; ni++) {
                int cb = (ni * 8 + g) * FST + kk * 8 + tg;
                unsigned bb[2] = {sKh[cb], sKh[cb + 4]};
                unsigned cc[2] = {sKl[cb], sKl[cb + 4]};
                mma16(s[0][ni], qh[0][kk], bb);
                mma16(s[1][ni], qh[1][kk], bb);
                mma16(s[0][ni], ql[0][kk], bb);
                mma16(s[1][ni], ql[1][kk], bb);
                mma16(s[0][ni], qh[0][kk], cc);
                mma16(s[1][ni], qh[1][kk], cc);
            }

        // mask bias + online softmax (rows: mi*16+g and mi*16+g+8)
#pragma unroll
        for (int mi = 0; mi < 2; mi++) {
            const float* mrow = mask + (n0 + wrow + mi * 16 + g) * 2048 + m0;
            float nm0 = -INFINITY, nm1 = -INFINITY;
#pragma unroll
            for (int ni = 0; ni < 8; ni++) {
                float2 mk0 = *(const float2*)(mrow + ni * 8 + tg * 2);
                float2 mk1 = *(const float2*)(mrow + 8 * 2048 + ni * 8 + tg * 2);
                s[mi][ni][0] += -1e10f * (1.f - mk0.x);
                s[mi][ni][1] += -1e10f * (1.f - mk0.y);
                s[mi][ni][2] += -1e10f * (1.f - mk1.x);
                s[mi][ni][3] += -1e10f * (1.f - mk1.y);
                nm0 = fmaxf(nm0, fmaxf(s[mi][ni][0], s[mi][ni][1]));
                nm1 = fmaxf(nm1, fmaxf(s[mi][ni][2], s[mi][ni][3]));
            }
            nm0 = fmaxf(nm0, __shfl_xor_sync(0xffffffffu, nm0, 1));
            nm0 = fmaxf(nm0, __shfl_xor_sync(0xffffffffu, nm0, 2));
            nm1 = fmaxf(nm1, __shfl_xor_sync(0xffffffffu, nm1, 1));
            nm1 = fmaxf(nm1, __shfl_xor_sync(0xffffffffu, nm1, 2));
            float mn0 = fmaxf(mr[mi][0], nm0), mn1 = fmaxf(mr[mi][1], nm1);
            float sc0 = __expf(mr[mi][0] - mn0), sc1 = __expf(mr[mi][1] - mn1);
            float rs0 = 0.f, rs1 = 0.f;
#pragma unroll
            for (int ni = 0; ni < 8; ni++) {
                s[mi][ni][0] = __expf(s[mi][ni][0] - mn0);
                s[mi][ni][1] = __expf(s[mi][ni][1] - mn0);
                s[mi][ni][2] = __expf(s[mi][ni][2] - mn1);
                s[mi][ni][3] = __expf(s[mi][ni][3] - mn1);
                rs0 += s[mi][ni][0] + s[mi][ni][1];
                rs1 += s[mi][ni][2] + s[mi][ni][3];
            }
            rs0 += __shfl_xor_sync(0xffffffffu, rs0, 1);
            rs0 += __shfl_xor_sync(0xffffffffu, rs0, 2);
            rs1 += __shfl_xor_sync(0xffffffffu, rs1, 1);
            rs1 += __shfl_xor_sync(0xffffffffu, rs1, 2);
            lr[mi][0] = lr[mi][0] * sc0 + rs0;
            lr[mi][1] = lr[mi][1] * sc1 + rs1;
            mr[mi][0] = mn0; mr[mi][1] = mn1;
#pragma unroll
            for (int eb = 0; eb < 8; eb++) {
                o[mi][eb][0] *= sc0; o[mi][eb][1] *= sc0;
                o[mi][eb][2] *= sc1; o[mi][eb][3] *= sc1;
            }
        }

        // P fragments directly from accumulators (acc layout == A-frag layout)
        unsigned ph[2][4][4], pl[2][4][4];
#pragma unroll
        for (int mi = 0; mi < 2; mi++)
#pragma unroll
            for (int kk = 0; kk < 4; kk++) {
                split2(s[mi][2 * kk][0],     s[mi][2 * kk][1],     ph[mi][kk][0], pl[mi][kk][0]);
                split2(s[mi][2 * kk][2],     s[mi][2 * kk][3],     ph[mi][kk][1], pl[mi][kk][1]);
                split2(s[mi][2 * kk + 1][0], s[mi][2 * kk + 1][1], ph[mi][kk][2], pl[mi][kk][2]);
                split2(s[mi][2 * kk + 1][2], s[mi][2 * kk + 1][3], ph[mi][kk][3], pl[mi][kk][3]);
            }

        // O += P V
#pragma unroll
        for (int kk = 0; kk < 4; kk++)
#pragma unroll
            for (int eb = 0; eb < 8; eb++) {
                int cb = (eb * 8 + g) * FST + kk * 8 + tg;
                unsigned bb[2] = {sVh[cb], sVh[cb + 4]};
                unsigned cc[2] = {sVl[cb], sVl[cb + 4]};
                mma16(o[0][eb], ph[0][kk], bb);
                mma16(o[1][eb], ph[1][kk], bb);
                mma16(o[0][eb], pl[0][kk], bb);
                mma16(o[1][eb], pl[1][kk], bb);
                mma16(o[0][eb], ph[0][kk], cc);
                mma16(o[1][eb], ph[1][kk], cc);
            }
    }

#pragma unroll
    for (int mi = 0; mi < 2; mi++) {
        float i0 = 1.f / lr[mi][0], i1 = 1.f / lr[mi][1];
        float* dst = g_ctx + (b * 2048 + n0 + wrow + mi * 16 + g) * DM + h * 64;
#pragma unroll
        for (int eb = 0; eb < 8; eb++) {
            int c = eb * 8 + tg * 2;
            *(float2*)(dst + c) = make_float2(o[mi][eb][0] * i0, o[mi][eb][1] * i0);
            *(float2*)(dst + 8 * DM + c) = make_float2(o[mi][eb][2] * i1, o[mi][eb][3] * i1);
        }
    }
}

extern "C" void kernel_launch(void* const* d_in, const int* in_sizes, int n_in,
                              void* d_out, int out_size) {
    const float* query = (const float*)d_in[0];
    const float* key   = (const float*)d_in[1];
    const float* value = (const float*)d_in[2];
    const float* mask  = (const float*)d_in[3];
    const float* Wq = (const float*)d_in[4];
    const float* bq = (const float*)d_in[5];
    const float* Wk = (const float*)d_in[6];
    const float* bk = (const float*)d_in[7];
    const float* Wv = (const float*)d_in[8];
    const float* bv = (const float*)d_in[9];
    const float* Wo = (const float*)d_in[10];
    const float* bo = (const float*)d_in[11];
    float* out = (float*)d_out;

    dim3 gg(8, 32);
    gemm128<1, 0, 0><<<gg, 256>>>(query, Wq, bq, nullptr, 0.125f);
    gemm128<1, 1, 0><<<gg, 256>>>(key,   Wk, bk, nullptr, 1.f);
    gemm128<1, 2, 0><<<gg, 256>>>(value, Wv, bv, nullptr, 1.f);
    flash_attn<<<dim3(16, 32), 128>>>(mask);
    gemm128<2, 3, 1><<<gg, 256>>>(nullptr, Wo, bo, out, 1.f);
}

// round 5
// speedup vs baseline: 1.2067x; 1.0273x over previous
#include <cuda_runtime.h>
#include <cuda_bf16.h>
#include <math.h>

#define DM 1024

__device__ float g_q[4096 * 1024];
__device__ float g_k[4096 * 1024];
__device__ float g_v[4096 * 1024];
__device__ float g_ctx[4096 * 1024];

__device__ __forceinline__ unsigned pk(__nv_bfloat16 a, __nv_bfloat16 b) {
    __nv_bfloat162 t; t.x = a; t.y = b;
    return *reinterpret_cast<unsigned*>(&t);
}
__device__ __forceinline__ void split2(float x, float y, unsigned& h, unsigned& l) {
    __nv_bfloat16 xh = __float2bfloat16(x), yh = __float2bfloat16(y);
    h = pk(xh, yh);
    l = pk(__float2bfloat16(x - __bfloat162float(xh)),
           __float2bfloat16(y - __bfloat162float(yh)));
}
__device__ __forceinline__ void mma16(float c[4], const unsigned a[4], const unsigned b[2]) {
    asm volatile(
        "mma.sync.aligned.m16n8k16.row.col.f32.bf16.bf16.f32 "
        "{%0,%1,%2,%3},{%4,%5,%6,%7},{%8,%9},{%0,%1,%2,%3};\n"
        : "+f"(c[0]), "+f"(c[1]), "+f"(c[2]), "+f"(c[3])
        : "r"(a[0]), "r"(a[1]), "r"(a[2]), "r"(a[3]), "r"(b[0]), "r"(b[1]));
}

// ============================================================================
// GEMM body: C[4096,1024] = alpha * (A @ B' + bias); double-buffered smem;
// B-frags loaded per-ni (low reg pressure -> 2 CTAs/SM).
// BMODE 1: B'[d][h*64+e] = W[h][d][e] ; BMODE 2: B'[h*64+e][n] = Wo[e*16+h][n]
// ============================================================================
#define AST 9

template <int BMODE>
__device__ __forceinline__ void gemm_body(const float* __restrict__ A,
                                          const float* __restrict__ Bw,
                                          const float* __restrict__ bias,
                                          float* __restrict__ C, float alpha) {
    __shared__ unsigned sAh[2][128 * AST], sAl[2][128 * AST];
    __shared__ unsigned sBh[2][128 * AST], sBl[2][128 * AST];

    const int tid = threadIdx.x, lane = tid & 31, warp = tid >> 5;
    const int wm = warp & 3, wn = warp >> 2, g = lane >> 2, tg = lane & 3;
    const int row0 = blockIdx.y * 128, col0 = blockIdx.x * 128;

    float acc[2][8][4] = {};
    float4 pa[2];
    float2 pb0[2], pb1[2];

    auto ldB = [&](int k, int n) -> float2 {
        const float* p;
        if (BMODE == 1) p = Bw + ((n >> 6) * DM + k) * 64 + (n & 63);
        else            p = Bw + ((k & 63) * 16 + (k >> 6)) * DM + n;
        return *(const float2*)p;
    };
    auto gload = [&](int kt) {
#pragma unroll
        for (int i = 0; i < 2; i++) {
            int s = tid + i * 256;
            pa[i] = *(const float4*)(A + (row0 + (s >> 2)) * DM + kt * 16 + (s & 3) * 4);
            int n = col0 + (s & 63) * 2;
            int k = kt * 16 + (s >> 6) * 2;
            pb0[i] = ldB(k, n);
            pb1[i] = ldB(k + 1, n);
        }
    };
    auto sstore = [&](int p) {
#pragma unroll
        for (int i = 0; i < 2; i++) {
            int s = tid + i * 256;
            int ar = s >> 2, aw = (s & 3) * 2;
            unsigned h0, l0, h1, l1;
            split2(pa[i].x, pa[i].y, h0, l0);
            split2(pa[i].z, pa[i].w, h1, l1);
            sAh[p][ar * AST + aw] = h0; sAh[p][ar * AST + aw + 1] = h1;
            sAl[p][ar * AST + aw] = l0; sAl[p][ar * AST + aw + 1] = l1;
            int n = (s & 63) * 2, kw = s >> 6;
            split2(pb0[i].x, pb1[i].x, h0, l0);
            split2(pb0[i].y, pb1[i].y, h1, l1);
            sBh[p][n * AST + kw] = h0;       sBl[p][n * AST + kw] = l0;
            sBh[p][(n + 1) * AST + kw] = h1; sBl[p][(n + 1) * AST + kw] = l1;
        }
    };

    gload(0); sstore(0); __syncthreads();

    for (int kt = 0; kt < 64; kt++) {
        const int p = kt & 1;
        if (kt < 63) gload(kt + 1);
        unsigned ah[2][4], al[2][4];
#pragma unroll
        for (int mi = 0; mi < 2; mi++) {
            int rb = (wm * 32 + mi * 16 + g) * AST + tg;
            ah[mi][0] = sAh[p][rb];     ah[mi][1] = sAh[p][rb + 8 * AST];
            ah[mi][2] = sAh[p][rb + 4]; ah[mi][3] = sAh[p][rb + 8 * AST + 4];
            al[mi][0] = sAl[p][rb];     al[mi][1] = sAl[p][rb + 8 * AST];
            al[mi][2] = sAl[p][rb + 4]; al[mi][3] = sAl[p][rb + 8 * AST + 4];
        }
#pragma unroll
        for (int ni = 0; ni < 8; ni++) {
            int cb = (wn * 64 + ni * 8 + g) * AST + tg;
            unsigned bh[2] = {sBh[p][cb], sBh[p][cb + 4]};
            unsigned bl[2] = {sBl[p][cb], sBl[p][cb + 4]};
            mma16(acc[0][ni], ah[0], bh);
            mma16(acc[1][ni], ah[1], bh);
            mma16(acc[0][ni], al[0], bh);
            mma16(acc[1][ni], al[1], bh);
            mma16(acc[0][ni], ah[0], bl);
            mma16(acc[1][ni], ah[1], bl);
        }
        if (kt < 63) sstore(p ^ 1);
        __syncthreads();
    }

#pragma unroll
    for (int mi = 0; mi < 2; mi++) {
        int r = row0 + wm * 32 + mi * 16 + g;
#pragma unroll
        for (int ni = 0; ni < 8; ni++) {
            int c = col0 + wn * 64 + ni * 8 + tg * 2;
            float2 bv = *(const float2*)(bias + c);
            *(float2*)(C + r * DM + c) =
                make_float2(alpha * (acc[mi][ni][0] + bv.x), alpha * (acc[mi][ni][1] + bv.y));
            *(float2*)(C + (r + 8) * DM + c) =
                make_float2(alpha * (acc[mi][ni][2] + bv.x), alpha * (acc[mi][ni][3] + bv.y));
        }
    }
}

__global__ void __launch_bounds__(256, 2)
gemm_qkv(const float* __restrict__ q, const float* __restrict__ k,
         const float* __restrict__ v,
         const float* __restrict__ Wq, const float* __restrict__ Wk,
         const float* __restrict__ Wv,
         const float* __restrict__ bq, const float* __restrict__ bk,
         const float* __restrict__ bv) {
    const int z = blockIdx.z;
    const float* A    = (z == 0) ? q  : (z == 1) ? k  : v;
    const float* Bw   = (z == 0) ? Wq : (z == 1) ? Wk : Wv;
    const float* bias = (z == 0) ? bq : (z == 1) ? bk : bv;
    float* C          = (z == 0) ? g_q : (z == 1) ? g_k : g_v;
    float alpha       = (z == 0) ? 0.125f : 1.f;
    gemm_body<1>(A, Bw, bias, C, alpha);
}

__global__ void __launch_bounds__(256, 2)
gemm_out(const float* __restrict__ Wo, const float* __restrict__ bo,
         float* __restrict__ out) {
    gemm_body<2>((const float*)g_ctx, Wo, bo, out, 1.f);
}

// ============================================================================
// Flash attention v3: CTA = 128 Q rows, 4 warps x 32 rows. Q frags in
// lane-private smem slots (no regs, no sync); P built per-kk from s.
// grid (16, 32), 128 threads, dynamic smem 68KB.
// ============================================================================
#define FST 36

__global__ void __launch_bounds__(128, 2) flash_attn(const float* __restrict__ mask) {
    extern __shared__ unsigned sm[];
    unsigned* sKh = sm;            // 2304 words
    unsigned* sKl = sm + 2304;
    unsigned* sVh = sm + 4608;     // V transposed [e][m] halves
    unsigned* sVl = sm + 6912;
    unsigned* sQh = sm + 9216;     // [warp][mi*4+kk][lane][4] = 4096 words
    unsigned* sQl = sm + 13312;

    const int tid = threadIdx.x, lane = tid & 31, warp = tid >> 5;
    const int g = lane >> 2, tg = lane & 3;
    const int bh = blockIdx.y, b = bh >> 4, h = bh & 15;
    const int n0 = blockIdx.x * 128, wrow = warp * 32;
    const int qbase = warp * 1024 + lane * 4;

    // Q fragments -> lane-private smem slots (STS.128, conflict-free)
    {
        const float* qb = g_q + (b * 2048 + n0 + wrow) * DM + h * 64;
#pragma unroll
        for (int mi = 0; mi < 2; mi++)
#pragma unroll
            for (int kk = 0; kk < 4; kk++) {
                int r0 = mi * 16 + g, r1 = r0 + 8, e = kk * 16 + 2 * tg;
                float2 x0 = *(const float2*)(qb + r0 * DM + e);
                float2 x1 = *(const float2*)(qb + r1 * DM + e);
                float2 x2 = *(const float2*)(qb + r0 * DM + e + 8);
                float2 x3 = *(const float2*)(qb + r1 * DM + e + 8);
                unsigned h0, l0, h1, l1, h2, l2, h3, l3;
                split2(x0.x, x0.y, h0, l0);
                split2(x1.x, x1.y, h1, l1);
                split2(x2.x, x2.y, h2, l2);
                split2(x3.x, x3.y, h3, l3);
                int a = qbase + (mi * 4 + kk) * 128;
                *(uint4*)(sQh + a) = make_uint4(h0, h1, h2, h3);
                *(uint4*)(sQl + a) = make_uint4(l0, l1, l2, l3);
            }
    }

    float o[2][8][4] = {};
    float mr[2][2] = {{-INFINITY, -INFINITY}, {-INFINITY, -INFINITY}};
    float lr[2][2] = {{0.f, 0.f}, {0.f, 0.f}};

    for (int mt = 0; mt < 32; mt++) {
        const int m0 = mt * 64;
        __syncthreads();  // previous PV done before K/V overwrite
        {   // K tile [m][e]
            int r = tid >> 1, e0 = (tid & 1) * 32;
            const float* ks = g_k + (b * 2048 + m0 + r) * DM + h * 64 + e0;
#pragma unroll
            for (int i = 0; i < 8; i++) {
                float4 v = *(const float4*)(ks + i * 4);
                unsigned h0, l0, h1, l1;
                split2(v.x, v.y, h0, l0); split2(v.z, v.w, h1, l1);
                int w = r * FST + (e0 + i * 4) / 2;
                sKh[w] = h0; sKh[w + 1] = h1; sKl[w] = l0; sKl[w + 1] = l1;
            }
            // V transposed
            int m = tid & 63, eh = (tid >> 6) * 32;
            const float* vs = g_v + (b * 2048 + m0 + m) * DM + h * 64 + eh;
            __nv_bfloat16* vh16 = (__nv_bfloat16*)sVh;
            __nv_bfloat16* vl16 = (__nv_bfloat16*)sVl;
#pragma unroll
            for (int i = 0; i < 8; i++) {
                float4 v = *(const float4*)(vs + i * 4);
                float xs[4] = {v.x, v.y, v.z, v.w};
#pragma unroll
                for (int j = 0; j < 4; j++) {
                    int e = eh + i * 4 + j;
                    __nv_bfloat16 hi = __float2bfloat16(xs[j]);
                    vh16[e * (2 * FST) + m] = hi;
                    vl16[e * (2 * FST) + m] = __float2bfloat16(xs[j] - __bfloat162float(hi));
                }
            }
        }
        __syncthreads();

        // S = Q K^T
        float s[2][8][4] = {};
#pragma unroll
        for (int kk = 0; kk < 4; kk++) {
            int a = qbase + kk * 128;
            uint4 qh0 = *(const uint4*)(sQh + a);
            uint4 ql0 = *(const uint4*)(sQl + a);
            uint4 qh1 = *(const uint4*)(sQh + a + 512);
            uint4 ql1 = *(const uint4*)(sQl + a + 512);
#pragma unroll
            for (int ni = 0; ni < 8; ni++) {
                int cb = (ni * 8 + g) * FST + kk * 8 + tg;
                unsigned bb[2] = {sKh[cb], sKh[cb + 4]};
                unsigned cc[2] = {sKl[cb], sKl[cb + 4]};
                mma16(s[0][ni], (const unsigned*)&qh0, bb);
                mma16(s[1][ni], (const unsigned*)&qh1, bb);
                mma16(s[0][ni], (const unsigned*)&ql0, bb);
                mma16(s[1][ni], (const unsigned*)&ql1, bb);
                mma16(s[0][ni], (const unsigned*)&qh0, cc);
                mma16(s[1][ni], (const unsigned*)&qh1, cc);
            }
        }

        // mask bias + online softmax
#pragma unroll
        for (int mi = 0; mi < 2; mi++) {
            const float* mrow = mask + (n0 + wrow + mi * 16 + g) * 2048 + m0;
            float nm0 = -INFINITY, nm1 = -INFINITY;
#pragma unroll
            for (int ni = 0; ni < 8; ni++) {
                float2 mk0 = *(const float2*)(mrow + ni * 8 + tg * 2);
                float2 mk1 = *(const float2*)(mrow + 8 * 2048 + ni * 8 + tg * 2);
                s[mi][ni][0] += -1e10f * (1.f - mk0.x);
                s[mi][ni][1] += -1e10f * (1.f - mk0.y);
                s[mi][ni][2] += -1e10f * (1.f - mk1.x);
                s[mi][ni][3] += -1e10f * (1.f - mk1.y);
                nm0 = fmaxf(nm0, fmaxf(s[mi][ni][0], s[mi][ni][1]));
                nm1 = fmaxf(nm1, fmaxf(s[mi][ni][2], s[mi][ni][3]));
            }
            nm0 = fmaxf(nm0, __shfl_xor_sync(0xffffffffu, nm0, 1));
            nm0 = fmaxf(nm0, __shfl_xor_sync(0xffffffffu, nm0, 2));
            nm1 = fmaxf(nm1, __shfl_xor_sync(0xffffffffu, nm1, 1));
            nm1 = fmaxf(nm1, __shfl_xor_sync(0xffffffffu, nm1, 2));
            float mn0 = fmaxf(mr[mi][0], nm0), mn1 = fmaxf(mr[mi][1], nm1);
            float sc0 = __expf(mr[mi][0] - mn0), sc1 = __expf(mr[mi][1] - mn1);
            float rs0 = 0.f, rs1 = 0.f;
#pragma unroll
            for (int ni = 0; ni < 8; ni++) {
                s[mi][ni][0] = __expf(s[mi][ni][0] - mn0);
                s[mi][ni][1] = __expf(s[mi][ni][1] - mn0);
                s[mi][ni][2] = __expf(s[mi][ni][2] - mn1);
                s[mi][ni][3] = __expf(s[mi][ni][3] - mn1);
                rs0 += s[mi][ni][0] + s[mi][ni][1];
                rs1 += s[mi][ni][2] + s[mi][ni][3];
            }
            rs0 += __shfl_xor_sync(0xffffffffu, rs0, 1);
            rs0 += __shfl_xor_sync(0xffffffffu, rs0, 2);
            rs1 += __shfl_xor_sync(0xffffffffu, rs1, 1);
            rs1 += __shfl_xor_sync(0xffffffffu, rs1, 2);
            lr[mi][0] = lr[mi][0] * sc0 + rs0;
            lr[mi][1] = lr[mi][1] * sc1 + rs1;
            mr[mi][0] = mn0; mr[mi][1] = mn1;
#pragma unroll
            for (int eb = 0; eb < 8; eb++) {
                o[mi][eb][0] *= sc0; o[mi][eb][1] *= sc0;
                o[mi][eb][2] *= sc1; o[mi][eb][3] *= sc1;
            }
        }

        // O += P V  (P frags built per-kk from s accumulators)
#pragma unroll
        for (int kk = 0; kk < 4; kk++) {
            unsigned ph[2][4], pl[2][4];
#pragma unroll
            for (int mi = 0; mi < 2; mi++) {
                split2(s[mi][2 * kk][0],     s[mi][2 * kk][1],     ph[mi][0], pl[mi][0]);
                split2(s[mi][2 * kk][2],     s[mi][2 * kk][3],     ph[mi][1], pl[mi][1]);
                split2(s[mi][2 * kk + 1][0], s[mi][2 * kk + 1][1], ph[mi][2], pl[mi][2]);
                split2(s[mi][2 * kk + 1][2], s[mi][2 * kk + 1][3], ph[mi][3], pl[mi][3]);
            }
#pragma unroll
            for (int eb = 0; eb < 8; eb++) {
                int cb = (eb * 8 + g) * FST + kk * 8 + tg;
                unsigned bb[2] = {sVh[cb], sVh[cb + 4]};
                unsigned cc[2] = {sVl[cb], sVl[cb + 4]};
                mma16(o[0][eb], ph[0], bb);
                mma16(o[1][eb], ph[1], bb);
                mma16(o[0][eb], pl[0], bb);
                mma16(o[1][eb], pl[1], bb);
                mma16(o[0][eb], ph[0], cc);
                mma16(o[1][eb], ph[1], cc);
            }
        }
    }

#pragma unroll
    for (int mi = 0; mi < 2; mi++) {
        float i0 = 1.f / lr[mi][0], i1 = 1.f / lr[mi][1];
        float* dst = g_ctx + (b * 2048 + n0 + wrow + mi * 16 + g) * DM + h * 64;
#pragma unroll
        for (int eb = 0; eb < 8; eb++) {
            int c = eb * 8 + tg * 2;
            *(float2*)(dst + c) = make_float2(o[mi][eb][0] * i0, o[mi][eb][1] * i0);
            *(float2*)(dst + 8 * DM + c) = make_float2(o[mi][eb][2] * i1, o[mi][eb][3] * i1);
        }
    }
}

extern "C" void kernel_launch(void* const* d_in, const int* in_sizes, int n_in,
                              void* d_out, int out_size) {
    const float* query = (const float*)d_in[0];
    const float* key   = (const float*)d_in[1];
    const float* value = (const float*)d_in[2];
    const float* mask  = (const float*)d_in[3];
    const float* Wq = (const float*)d_in[4];
    const float* bq = (const float*)d_in[5];
    const float* Wk = (const float*)d_in[6];
    const float* bk = (const float*)d_in[7];
    const float* Wv = (const float*)d_in[8];
    const float* bv = (const float*)d_in[9];
    const float* Wo = (const float*)d_in[10];
    const float* bo = (const float*)d_in[11];
    float* out = (float*)d_out;

    cudaFuncSetAttribute(flash_attn, cudaFuncAttributeMaxDynamicSharedMemorySize, 69632);

    gemm_qkv<<<dim3(8, 32, 3), 256>>>(query, key, value, Wq, Wk, Wv, bq, bk, bv);
    flash_attn<<<dim3(16, 32), 128, 69632>>>(mask);
    gemm_out<<<dim3(8, 32), 256>>>(Wo, bo, out);
}